// round 14
// baseline (speedup 1.0000x reference)
#include <cuda_runtime.h>
#include <cuda_fp16.h>
#include <cstdint>

#define B_    2
#define N_    16384
#define M_    16384
#define K_    32
#define CIN   64
#define COUT  128
#define KS_   15
#define JC    960
#define QT    32
#define NTH   256
#define SH    968            // s_h row stride (halves)
#define FSTR  72             // F-buf row stride (halves) = 144B
#define ISTRH 40             // I-buf row stride (halves) = 80B
#define NTILES (B_ * (N_ / QT))   // 1024
#define GRID_MAIN 296             // 2 CTAs x 148 SMs = one full wave

typedef unsigned long long ull;
typedef uint32_t u32;

// ---------------- HMMA m16n8k16 + LDSM + cp.async (baseline PTX) --------------
__device__ __forceinline__ void mma16816(float& d0, float& d1, float& d2, float& d3,
                                         u32 a0, u32 a1, u32 a2, u32 a3,
                                         u32 b0, u32 b1) {
    asm volatile(
        "mma.sync.aligned.m16n8k16.row.col.f32.f16.f16.f32 "
        "{%0,%1,%2,%3}, {%4,%5,%6,%7}, {%8,%9}, {%0,%1,%2,%3};"
        : "+f"(d0), "+f"(d1), "+f"(d2), "+f"(d3)
        : "r"(a0), "r"(a1), "r"(a2), "r"(a3), "r"(b0), "r"(b1));
}
__device__ __forceinline__ void ldsm_x4(u32& r0, u32& r1, u32& r2, u32& r3,
                                        u32 addr) {
    asm volatile("ldmatrix.sync.aligned.m8n8.x4.shared.b16 {%0,%1,%2,%3}, [%4];"
                 : "=r"(r0), "=r"(r1), "=r"(r2), "=r"(r3) : "r"(addr));
}
__device__ __forceinline__ void ldsm_x4_t(u32& r0, u32& r1, u32& r2, u32& r3,
                                          u32 addr) {
    asm volatile("ldmatrix.sync.aligned.m8n8.x4.trans.shared.b16 {%0,%1,%2,%3}, [%4];"
                 : "=r"(r0), "=r"(r1), "=r"(r2), "=r"(r3) : "r"(addr));
}
__device__ __forceinline__ u32 smem_u32(const void* p) {
    u32 a;
    asm("{ .reg .u64 t; cvta.to.shared.u64 t, %1; cvt.u32.u64 %0, t; }"
        : "=r"(a) : "l"(p));
    return a;
}
__device__ __forceinline__ void cp_async16(u32 saddr, const void* gptr) {
    asm volatile("cp.async.cg.shared.global [%0], [%1], 16;"
                 :: "r"(saddr), "l"(gptr));
}
__device__ __forceinline__ void cp_async_wait_all() {
    asm volatile("cp.async.wait_all;" ::: "memory");
}

// ---------------- pre-packed global images ----------------
__device__ __align__(16) u32    g_Wfrag[60 * 4 * 32 * 8];   // W in B-frag layout
__device__ __align__(16) __half g_sf16[B_ * M_ * CIN];      // fp16 features
__device__ __align__(16) float4 g_sp4[B_ * M_];             // xyz0 positions

// ---------------- merged conversion prologue (one kernel) ----------------
#define CVT_SF_N   (B_ * M_ * 8)                 // 262144
#define CVT_SP_N   (B_ * M_)                     // 32768
#define CVT_W_N    (60 * 4 * 32 * 4)             // 30720
#define CVT_TOTAL  (CVT_SF_N + CVT_SP_N + CVT_W_N)

__global__ void convert_all(const float* __restrict__ W,
                            const float* __restrict__ sf,
                            const float* __restrict__ sp) {
    const int t = blockIdx.x * blockDim.x + threadIdx.x;
    if (t < CVT_SF_N) {
        const size_t base = (size_t)t * 8;
        const float4 f0 = *(const float4*)(sf + base);
        const float4 f1 = *(const float4*)(sf + base + 4);
        __half2 h0 = __floats2half2_rn(f0.x, f0.y);
        __half2 h1 = __floats2half2_rn(f0.z, f0.w);
        __half2 h2 = __floats2half2_rn(f1.x, f1.y);
        __half2 h3 = __floats2half2_rn(f1.z, f1.w);
        uint4 v;
        v.x = *reinterpret_cast<u32*>(&h0);
        v.y = *reinterpret_cast<u32*>(&h1);
        v.z = *reinterpret_cast<u32*>(&h2);
        v.w = *reinterpret_cast<u32*>(&h3);
        *(uint4*)(g_sf16 + base) = v;
    } else if (t < CVT_SF_N + CVT_SP_N) {
        const int i = t - CVT_SF_N;
        g_sp4[i] = make_float4(sp[3 * i], sp[3 * i + 1], sp[3 * i + 2], 0.f);
    } else if (t < CVT_TOTAL) {
        const int w = t - (CVT_SF_N + CVT_SP_N);
        const int nt   = w & 3;
        const int lane = (w >> 2) & 31;
        const int ot   = (w >> 7) & 3;
        const int ks   = w >> 9;
        const int o    = ot * 32 + nt * 8 + (lane >> 2);
        u32 b[2];
        #pragma unroll
        for (int reg = 0; reg < 2; ++reg) {
            __half hh[2];
            #pragma unroll
            for (int u = 0; u < 2; ++u) {
                const int jcp = ks * 16 + reg * 8 + (lane & 3) * 2 + u;
                const int g   = jcp / 30;
                const int rem = jcp - g * 30;
                const int j   = rem >> 1;
                const int uu  = rem & 1;
                const int c   = (g >> 2) * 8 + (g & 3) * 2 + uu;
                hh[u] = __float2half_rn(W[(size_t)(j * 64 + c) * COUT + o]);
            }
            __half2 p = __halves2half2(hh[0], hh[1]);
            b[reg] = *reinterpret_cast<u32*>(&p);
        }
        u32* dst = g_Wfrag + ((size_t)((ks * 4 + ot) * 32 + lane)) * 8 + nt * 2;
        dst[0] = b[0];
        dst[1] = b[1];
    }
}

// ---------------- smem layout (bytes) ----------------
#define SM_H    0                    // 32 * 968 * 2          = 61952
#define SM_F    61952                // 8 * 32 * 144          = 36864  (reused for reduction)
#define SM_I    98816                // 8 * 16 * 80           = 10240
#define SM_BIAS 109056               // 512
#define SM_QP   109568               // 384
#define SM_KP   109952               // 192
#define SMEM_TOTAL 110208

__global__ __launch_bounds__(NTH, 2)
void kpconv_main(const float* __restrict__ qp,
                 const int*   __restrict__ nidx,
                 const float* __restrict__ kp,
                 const float* __restrict__ bias,
                 float*       __restrict__ out)
{
    extern __shared__ char smem[];
    const int tid  = threadIdx.x;
    const int wid  = tid >> 5;
    const int lane = tid & 31;

    float* s_qp   = (float*)(smem + SM_QP);
    float* s_kp   = (float*)(smem + SM_KP);
    float* s_bias = (float*)(smem + SM_BIAS);

    if (tid < KS_ * 3) s_kp[tid] = kp[tid];
    if (tid < COUT)    s_bias[tid] = bias[tid];

    const u32 sbase = smem_u32(smem);

    // stage identities (loop-invariant)
    const int ot    = wid & 3;
    const int khalf = wid >> 2;
    const int ksb   = khalf * 30;
    const int o0    = ot * 32;
    const uint4* wf = reinterpret_cast<const uint4*>(g_Wfrag)
                    + ((size_t)ot * 32 + lane) * 2;

    __half* Ib = (__half*)(smem + SM_I) + wid * (16 * ISTRH);
    const u32 fb_u = sbase + SM_F + wid * (32 * FSTR * 2);
    const u32 ib_u = sbase + SM_I + wid * (16 * ISTRH * 2);
    Ib[15 * ISTRH + lane] = __float2half(0.0f);     // padded j=15 row (persists)

    // ============ persistent loop over q-tiles ============
    #pragma unroll 1
    for (int tile = blockIdx.x; tile < NTILES; tile += GRID_MAIN) {
        const int b  = tile >> 9;
        const int q0 = (tile & 511) * QT;

        if (tid < QT * 3)
            s_qp[tid] = qp[(size_t)(b * N_ + q0) * 3 + tid];

        // batch all 4 neighbor-index loads up front (MLP 4 on the index chain)
        int myidx4[4];
        {
            const int* np = nidx + ((size_t)(b * N_ + q0 + wid * 4)) * K_ + lane;
            #pragma unroll
            for (int qi = 0; qi < 4; ++qi)
                myidx4[qi] = np[qi * K_];
        }
        __syncthreads();   // s_qp visible; prior tile's F-region reads complete

        // ---- fused Stage A + Stage B (HMMA) : h -> s_h (permuted fp16) ----
        #pragma unroll 1
        for (int qi = 0; qi < 4; ++qi) {
            const int q = wid * 4 + qi;
            const int myidx = myidx4[qi];

            // gather fp16 features F[k][c] via cp.async
            {
                const __half* sfb = g_sf16 + (size_t)b * M_ * CIN + (lane & 7) * 8;
                const int sub = lane >> 3;
                const u32 fdst = fb_u + (lane & 7) * 16;
                #pragma unroll
                for (int it = 0; it < 8; ++it) {
                    const int kk  = it * 4 + sub;
                    const int idx = __shfl_sync(0xffffffffu, myidx, kk);
                    cp_async16(fdst + kk * (FSTR * 2), sfb + (size_t)idx * CIN);
                }
            }

            // Stage A: lane = neighbor k; fp16 influences I[j][k]
            {
                const float4 p4 = g_sp4[(size_t)b * M_ + myidx];
                const float rx = p4.x - s_qp[q * 3 + 0];
                const float ry = p4.y - s_qp[q * 3 + 1];
                const float rz = p4.z - s_qp[q * 3 + 2];
                float e[KS_];
                float sum = 0.f;
                #pragma unroll
                for (int j = 0; j < KS_; ++j) {
                    const float dx = rx - s_kp[j * 3 + 0];
                    const float dy = ry - s_kp[j * 3 + 1];
                    const float dz = rz - s_kp[j * 3 + 2];
                    const float d2 = dx * dx + dy * dy + dz * dz;
                    e[j] = __expf(-200.0f * d2);        // sigma = 0.05
                    sum += e[j];
                }
                const float inv = 1.0f / (sum + 1e-6f);
                #pragma unroll
                for (int j = 0; j < KS_; ++j)
                    Ib[j * ISTRH + lane] = __float2half_rn(e[j] * inv);
            }
            cp_async_wait_all();
            __syncwarp();

            // MMA: h[16j][64c] = I[16j][32k] * F[32k][64c]
            u32 aI[2][4];
            ldsm_x4(aI[0][0], aI[0][1], aI[0][2], aI[0][3],
                    ib_u + (lane & 15) * (ISTRH * 2) + (lane >> 4) * 16);
            ldsm_x4(aI[1][0], aI[1][1], aI[1][2], aI[1][3],
                    ib_u + (lane & 15) * (ISTRH * 2) + (lane >> 4) * 16 + 32);

            float acc[8][4];
            #pragma unroll
            for (int nt = 0; nt < 8; ++nt)
                #pragma unroll
                for (int i = 0; i < 4; ++i) acc[nt][i] = 0.f;

            #pragma unroll
            for (int cp = 0; cp < 4; ++cp) {
                #pragma unroll
                for (int k2 = 0; k2 < 2; ++k2) {
                    u32 b0, b1, b2, b3;
                    ldsm_x4_t(b0, b1, b2, b3,
                              fb_u + (u32)(k2 * 16 + (lane & 15)) * (FSTR * 2)
                                   + (u32)(cp * 16 + (lane >> 4) * 8) * 2);
                    mma16816(acc[cp*2][0], acc[cp*2][1], acc[cp*2][2], acc[cp*2][3],
                             aI[k2][0], aI[k2][1], aI[k2][2], aI[k2][3], b0, b1);
                    mma16816(acc[cp*2+1][0], acc[cp*2+1][1], acc[cp*2+1][2], acc[cp*2+1][3],
                             aI[k2][0], aI[k2][1], aI[k2][2], aI[k2][3], b2, b3);
                }
            }

            // writeback h (permuted columns, fp16)
            {
                char* hq = smem + SM_H + (size_t)q * (SH * 2);
                const int g = lane >> 2;
                const int t = lane & 3;
                #pragma unroll
                for (int nt = 0; nt < 8; ++nt) {
                    const int off = (nt * 4 + t) * 60 + g * 4;
                    *(__half2*)(hq + off) =
                        __floats2half2_rn(acc[nt][0], acc[nt][1]);
                    if (g != 7)
                        *(__half2*)(hq + off + 32) =
                            __floats2half2_rn(acc[nt][2], acc[nt][3]);
                }
            }
            __syncwarp();
        }
        __syncthreads();

        // ---- Stage C: split-K GEMM, warp = 32q x 32o x 30ks ----
        {
            const u32 a0_addr = sbase + SM_H
                              + (u32)(lane & 15) * (SH * 2) + (u32)(lane >> 4) * 16;
            const u32 a1_addr = a0_addr + 16 * (SH * 2);

            float acc[2][4][4];
            #pragma unroll
            for (int qt = 0; qt < 2; ++qt)
                #pragma unroll
                for (int nt = 0; nt < 4; ++nt)
                    #pragma unroll
                    for (int i = 0; i < 4; ++i) acc[qt][nt][i] = 0.f;

            #pragma unroll 3
            for (int ks = 0; ks < 30; ++ks) {
                const int gks = ksb + ks;
                const uint4 w0 = wf[(size_t)gks * 256];
                const uint4 w1 = wf[(size_t)gks * 256 + 1];
                u32 x0, x1, x2, x3, y0, y1, y2, y3;
                ldsm_x4(x0, x1, x2, x3, a0_addr + gks * 32);
                ldsm_x4(y0, y1, y2, y3, a1_addr + gks * 32);
                mma16816(acc[0][0][0], acc[0][0][1], acc[0][0][2], acc[0][0][3],
                         x0, x1, x2, x3, w0.x, w0.y);
                mma16816(acc[0][1][0], acc[0][1][1], acc[0][1][2], acc[0][1][3],
                         x0, x1, x2, x3, w0.z, w0.w);
                mma16816(acc[0][2][0], acc[0][2][1], acc[0][2][2], acc[0][2][3],
                         x0, x1, x2, x3, w1.x, w1.y);
                mma16816(acc[0][3][0], acc[0][3][1], acc[0][3][2], acc[0][3][3],
                         x0, x1, x2, x3, w1.z, w1.w);
                mma16816(acc[1][0][0], acc[1][0][1], acc[1][0][2], acc[1][0][3],
                         y0, y1, y2, y3, w0.x, w0.y);
                mma16816(acc[1][1][0], acc[1][1][1], acc[1][1][2], acc[1][1][3],
                         y0, y1, y2, y3, w0.z, w0.w);
                mma16816(acc[1][2][0], acc[1][2][1], acc[1][2][2], acc[1][2][3],
                         y0, y1, y2, y3, w1.x, w1.y);
                mma16816(acc[1][3][0], acc[1][3][1], acc[1][3][2], acc[1][3][3],
                         y0, y1, y2, y3, w1.z, w1.w);
            }

            __syncthreads();   // s_h consumed; F region reusable for reduction

            // symmetric split epilogue:
            //   khalf==1 publishes qt=0 partials -> red0; khalf==0 publishes qt=1 -> red1
            //   then khalf==0 finalizes qt=0 rows, khalf==1 finalizes qt=1 rows
            float* red0 = (float*)(smem + SM_F);            // [16 i][4 ot][32 lane]
            float* red1 = red0 + 16 * 4 * 32;
            {
                float* dst = (khalf == 1) ? red0 : red1;
                const int qsrc = (khalf == 1) ? 0 : 1;
                #pragma unroll
                for (int i = 0; i < 16; ++i)
                    dst[(i * 4 + ot) * 32 + lane] = acc[qsrc][i >> 2][i & 3];
            }
            __syncthreads();

            {
                const float* src  = (khalf == 0) ? red0 : red1;
                const int    qt   = khalf;         // my output half
                const int gid = lane >> 2;
                const int tig = lane & 3;
                const int qA  = q0 + qt * 16 + gid;
                #pragma unroll
                for (int nt = 0; nt < 4; ++nt) {
                    const int o = o0 + nt * 8 + tig * 2;
                    const float2 bv = *(const float2*)(s_bias + o);
                    const int ib = nt * 4;
                    float2 r0, r1;
                    r0.x = acc[qt][nt][0] + src[((ib + 0) * 4 + ot) * 32 + lane] + bv.x;
                    r0.y = acc[qt][nt][1] + src[((ib + 1) * 4 + ot) * 32 + lane] + bv.y;
                    r1.x = acc[qt][nt][2] + src[((ib + 2) * 4 + ot) * 32 + lane] + bv.x;
                    r1.y = acc[qt][nt][3] + src[((ib + 3) * 4 + ot) * 32 + lane] + bv.y;
                    *(float2*)(out + ((size_t)(b * N_ + qA))     * COUT + o) = r0;
                    *(float2*)(out + ((size_t)(b * N_ + qA + 8)) * COUT + o) = r1;
                }
            }
        }
        // loop-top __syncthreads() of next iteration provides cross-tile safety
    }
}

// ---------------- launch ----------------
extern "C" void kernel_launch(void* const* d_in, const int* in_sizes, int n_in,
                              void* d_out, int out_size) {
    const float* qp   = (const float*)d_in[0];
    const float* sp   = (const float*)d_in[1];
    const float* sf   = (const float*)d_in[2];
    const int*   nidx = (const int*)  d_in[3];
    const float* kp   = (const float*)d_in[4];
    const float* W    = (const float*)d_in[5];
    const float* bias = (const float*)d_in[6];
    float* out = (float*)d_out;

    static bool attr_set = false;
    if (!attr_set) {
        cudaFuncSetAttribute(kpconv_main,
                             cudaFuncAttributeMaxDynamicSharedMemorySize,
                             SMEM_TOTAL);
        attr_set = true;
    }

    convert_all<<<(CVT_TOTAL + 255) / 256, 256>>>(W, sf, sp);
    kpconv_main<<<GRID_MAIN, NTH, SMEM_TOTAL>>>(qp, nidx, kp, bias, out);
}

// round 16
// speedup vs baseline: 1.7466x; 1.7466x over previous
#include <cuda_runtime.h>
#include <cuda_fp16.h>
#include <cstdint>

#define B_    2
#define N_    16384
#define M_    16384
#define K_    32
#define CIN   64
#define COUT  128
#define KS_   15
#define JC    960
#define QT    32
#define NTH   256
#define SH    968            // s_h row stride (halves)
#define FSTR  72             // F-buf row stride (halves) = 144B
#define ISTRH 40             // I-buf row stride (halves) = 80B
#define NTILES (B_ * (N_ / QT))   // 1024
#define GRID_MAIN 296             // 2 CTAs x 148 SMs = one full wave

typedef unsigned long long ull;
typedef uint32_t u32;

// ---------------- HMMA m16n8k16 + LDSM + cp.async (baseline PTX) --------------
__device__ __forceinline__ void mma16816(float& d0, float& d1, float& d2, float& d3,
                                         u32 a0, u32 a1, u32 a2, u32 a3,
                                         u32 b0, u32 b1) {
    asm volatile(
        "mma.sync.aligned.m16n8k16.row.col.f32.f16.f16.f32 "
        "{%0,%1,%2,%3}, {%4,%5,%6,%7}, {%8,%9}, {%0,%1,%2,%3};"
        : "+f"(d0), "+f"(d1), "+f"(d2), "+f"(d3)
        : "r"(a0), "r"(a1), "r"(a2), "r"(a3), "r"(b0), "r"(b1));
}
__device__ __forceinline__ void ldsm_x4(u32& r0, u32& r1, u32& r2, u32& r3,
                                        u32 addr) {
    asm volatile("ldmatrix.sync.aligned.m8n8.x4.shared.b16 {%0,%1,%2,%3}, [%4];"
                 : "=r"(r0), "=r"(r1), "=r"(r2), "=r"(r3) : "r"(addr));
}
__device__ __forceinline__ void ldsm_x4_t(u32& r0, u32& r1, u32& r2, u32& r3,
                                          u32 addr) {
    asm volatile("ldmatrix.sync.aligned.m8n8.x4.trans.shared.b16 {%0,%1,%2,%3}, [%4];"
                 : "=r"(r0), "=r"(r1), "=r"(r2), "=r"(r3) : "r"(addr));
}
__device__ __forceinline__ u32 smem_u32(const void* p) {
    u32 a;
    asm("{ .reg .u64 t; cvta.to.shared.u64 t, %1; cvt.u32.u64 %0, t; }"
        : "=r"(a) : "l"(p));
    return a;
}
__device__ __forceinline__ void cp_async16(u32 saddr, const void* gptr) {
    asm volatile("cp.async.cg.shared.global [%0], [%1], 16;"
                 :: "r"(saddr), "l"(gptr));
}
__device__ __forceinline__ void cp_async_wait_all() {
    asm volatile("cp.async.wait_all;" ::: "memory");
}

// ---------------- pre-packed global images ----------------
__device__ __align__(16) u32    g_Wfrag[60 * 4 * 32 * 8];   // W in B-frag layout
__device__ __align__(16) __half g_sf16[B_ * M_ * CIN];      // fp16 features
__device__ __align__(16) float4 g_sp4[B_ * M_];             // xyz0 positions

// ---------------- merged conversion prologue (one kernel) ----------------
#define CVT_SF_N   (B_ * M_ * 8)                 // 262144
#define CVT_SP_N   (B_ * M_)                     // 32768
#define CVT_W_N    (60 * 4 * 32 * 4)             // 30720
#define CVT_TOTAL  (CVT_SF_N + CVT_SP_N + CVT_W_N)

__global__ void convert_all(const float* __restrict__ W,
                            const float* __restrict__ sf,
                            const float* __restrict__ sp) {
    const int t = blockIdx.x * blockDim.x + threadIdx.x;
    if (t < CVT_SF_N) {
        const size_t base = (size_t)t * 8;
        const float4 f0 = *(const float4*)(sf + base);
        const float4 f1 = *(const float4*)(sf + base + 4);
        __half2 h0 = __floats2half2_rn(f0.x, f0.y);
        __half2 h1 = __floats2half2_rn(f0.z, f0.w);
        __half2 h2 = __floats2half2_rn(f1.x, f1.y);
        __half2 h3 = __floats2half2_rn(f1.z, f1.w);
        uint4 v;
        v.x = *reinterpret_cast<u32*>(&h0);
        v.y = *reinterpret_cast<u32*>(&h1);
        v.z = *reinterpret_cast<u32*>(&h2);
        v.w = *reinterpret_cast<u32*>(&h3);
        *(uint4*)(g_sf16 + base) = v;
    } else if (t < CVT_SF_N + CVT_SP_N) {
        const int i = t - CVT_SF_N;
        g_sp4[i] = make_float4(sp[3 * i], sp[3 * i + 1], sp[3 * i + 2], 0.f);
    } else if (t < CVT_TOTAL) {
        const int w = t - (CVT_SF_N + CVT_SP_N);
        const int nt   = w & 3;
        const int lane = (w >> 2) & 31;
        const int ot   = (w >> 7) & 3;
        const int ks   = w >> 9;
        const int o    = ot * 32 + nt * 8 + (lane >> 2);
        u32 b[2];
        #pragma unroll
        for (int reg = 0; reg < 2; ++reg) {
            __half hh[2];
            #pragma unroll
            for (int u = 0; u < 2; ++u) {
                const int jcp = ks * 16 + reg * 8 + (lane & 3) * 2 + u;
                const int g   = jcp / 30;
                const int rem = jcp - g * 30;
                const int j   = rem >> 1;
                const int uu  = rem & 1;
                const int c   = (g >> 2) * 8 + (g & 3) * 2 + uu;
                hh[u] = __float2half_rn(W[(size_t)(j * 64 + c) * COUT + o]);
            }
            __half2 p = __halves2half2(hh[0], hh[1]);
            b[reg] = *reinterpret_cast<u32*>(&p);
        }
        u32* dst = g_Wfrag + ((size_t)((ks * 4 + ot) * 32 + lane)) * 8 + nt * 2;
        dst[0] = b[0];
        dst[1] = b[1];
    }
}

// ---------------- smem layout (bytes) ----------------
#define SM_H    0                    // 32 * 968 * 2          = 61952
#define SM_F    61952                // 8 * 32 * 144          = 36864  (reused for reduction)
#define SM_I    98816                // 8 * 16 * 80           = 10240
#define SM_BIAS 109056               // 512
#define SM_QP   109568               // 384
#define SM_KP   109952               // 192
#define SMEM_TOTAL 110208

__global__ __launch_bounds__(NTH, 2)
void kpconv_main(const float* __restrict__ qp,
                 const int*   __restrict__ nidx,
                 const float* __restrict__ kp,
                 const float* __restrict__ bias,
                 float*       __restrict__ out)
{
    extern __shared__ char smem[];
    const int tid  = threadIdx.x;
    const int wid  = tid >> 5;
    const int lane = tid & 31;

    float* s_qp   = (float*)(smem + SM_QP);
    float* s_kp   = (float*)(smem + SM_KP);
    float* s_bias = (float*)(smem + SM_BIAS);

    if (tid < KS_ * 3) s_kp[tid] = kp[tid];
    if (tid < COUT)    s_bias[tid] = bias[tid];

    const u32 sbase = smem_u32(smem);

    // stage identities (loop-invariant)
    const int ot    = wid & 3;
    const int khalf = wid >> 2;
    const int ksb   = khalf * 30;
    const int o0    = ot * 32;
    const uint4* wf = reinterpret_cast<const uint4*>(g_Wfrag)
                    + ((size_t)ot * 32 + lane) * 2;

    __half* Ib = (__half*)(smem + SM_I) + wid * (16 * ISTRH);
    const u32 fb_u = sbase + SM_F + wid * (32 * FSTR * 2);
    const u32 ib_u = sbase + SM_I + wid * (16 * ISTRH * 2);
    Ib[15 * ISTRH + lane] = __float2half(0.0f);     // padded j=15 row (persists)

    // ============ persistent loop over q-tiles ============
    #pragma unroll 1
    for (int tile = blockIdx.x; tile < NTILES; tile += GRID_MAIN) {
        const int b  = tile >> 9;
        const int q0 = (tile & 511) * QT;

        if (tid < QT * 3)
            s_qp[tid] = qp[(size_t)(b * N_ + q0) * 3 + tid];

        // prime the scalar pipeline: qi=0 index + position (cover under barrier)
        int    curidx = nidx[((size_t)(b * N_ + q0 + wid * 4)) * K_ + lane];
        float4 curp4  = g_sp4[(size_t)b * M_ + curidx];
        __syncthreads();   // s_qp visible; prior tile's F-region reads complete

        // ---- fused Stage A + Stage B (HMMA) : h -> s_h (permuted fp16) ----
        #pragma unroll 1
        for (int qi = 0; qi < 4; ++qi) {
            const int q = wid * 4 + qi;

            // prefetch next qi's neighbor index (scalar, stays in a register)
            int nxtidx = curidx;
            if (qi < 3)
                nxtidx = nidx[((size_t)(b * N_ + q0 + q + 1)) * K_ + lane];

            // gather fp16 features F[k][c] via cp.async (uses curidx)
            {
                const __half* sfb = g_sf16 + (size_t)b * M_ * CIN + (lane & 7) * 8;
                const int sub = lane >> 3;
                const u32 fdst = fb_u + (lane & 7) * 16;
                #pragma unroll
                for (int it = 0; it < 8; ++it) {
                    const int kk  = it * 4 + sub;
                    const int idx = __shfl_sync(0xffffffffu, curidx, kk);
                    cp_async16(fdst + kk * (FSTR * 2), sfb + (size_t)idx * CIN);
                }
            }

            // prefetch next qi's position (retires under stage A + MMA below)
            float4 nxtp4 = curp4;
            if (qi < 3)
                nxtp4 = g_sp4[(size_t)b * M_ + nxtidx];

            // Stage A: lane = neighbor k; fp16 influences I[j][k]
            {
                const float rx = curp4.x - s_qp[q * 3 + 0];
                const float ry = curp4.y - s_qp[q * 3 + 1];
                const float rz = curp4.z - s_qp[q * 3 + 2];
                float e[KS_];
                float sum = 0.f;
                #pragma unroll
                for (int j = 0; j < KS_; ++j) {
                    const float dx = rx - s_kp[j * 3 + 0];
                    const float dy = ry - s_kp[j * 3 + 1];
                    const float dz = rz - s_kp[j * 3 + 2];
                    const float d2 = dx * dx + dy * dy + dz * dz;
                    e[j] = __expf(-200.0f * d2);        // sigma = 0.05
                    sum += e[j];
                }
                const float inv = 1.0f / (sum + 1e-6f);
                #pragma unroll
                for (int j = 0; j < KS_; ++j)
                    Ib[j * ISTRH + lane] = __float2half_rn(e[j] * inv);
            }
            cp_async_wait_all();
            __syncwarp();

            // MMA: h[16j][64c] = I[16j][32k] * F[32k][64c]
            u32 aI[2][4];
            ldsm_x4(aI[0][0], aI[0][1], aI[0][2], aI[0][3],
                    ib_u + (lane & 15) * (ISTRH * 2) + (lane >> 4) * 16);
            ldsm_x4(aI[1][0], aI[1][1], aI[1][2], aI[1][3],
                    ib_u + (lane & 15) * (ISTRH * 2) + (lane >> 4) * 16 + 32);

            float acc[8][4];
            #pragma unroll
            for (int nt = 0; nt < 8; ++nt)
                #pragma unroll
                for (int i = 0; i < 4; ++i) acc[nt][i] = 0.f;

            #pragma unroll
            for (int cp = 0; cp < 4; ++cp) {
                #pragma unroll
                for (int k2 = 0; k2 < 2; ++k2) {
                    u32 b0, b1, b2, b3;
                    ldsm_x4_t(b0, b1, b2, b3,
                              fb_u + (u32)(k2 * 16 + (lane & 15)) * (FSTR * 2)
                                   + (u32)(cp * 16 + (lane >> 4) * 8) * 2);
                    mma16816(acc[cp*2][0], acc[cp*2][1], acc[cp*2][2], acc[cp*2][3],
                             aI[k2][0], aI[k2][1], aI[k2][2], aI[k2][3], b0, b1);
                    mma16816(acc[cp*2+1][0], acc[cp*2+1][1], acc[cp*2+1][2], acc[cp*2+1][3],
                             aI[k2][0], aI[k2][1], aI[k2][2], aI[k2][3], b2, b3);
                }
            }

            // writeback h (permuted columns, fp16)
            {
                char* hq = smem + SM_H + (size_t)q * (SH * 2);
                const int g = lane >> 2;
                const int t = lane & 3;
                #pragma unroll
                for (int nt = 0; nt < 8; ++nt) {
                    const int off = (nt * 4 + t) * 60 + g * 4;
                    *(__half2*)(hq + off) =
                        __floats2half2_rn(acc[nt][0], acc[nt][1]);
                    if (g != 7)
                        *(__half2*)(hq + off + 32) =
                            __floats2half2_rn(acc[nt][2], acc[nt][3]);
                }
            }
            __syncwarp();

            curidx = nxtidx;   // rotate scalar pipeline
            curp4  = nxtp4;
        }
        __syncthreads();

        // ---- Stage C: split-K GEMM, warp = 32q x 32o x 30ks ----
        {
            const u32 a0_addr = sbase + SM_H
                              + (u32)(lane & 15) * (SH * 2) + (u32)(lane >> 4) * 16;
            const u32 a1_addr = a0_addr + 16 * (SH * 2);

            float acc[2][4][4];
            #pragma unroll
            for (int qt = 0; qt < 2; ++qt)
                #pragma unroll
                for (int nt = 0; nt < 4; ++nt)
                    #pragma unroll
                    for (int i = 0; i < 4; ++i) acc[qt][nt][i] = 0.f;

            #pragma unroll 3
            for (int ks = 0; ks < 30; ++ks) {
                const int gks = ksb + ks;
                const uint4 w0 = wf[(size_t)gks * 256];
                const uint4 w1 = wf[(size_t)gks * 256 + 1];
                u32 x0, x1, x2, x3, y0, y1, y2, y3;
                ldsm_x4(x0, x1, x2, x3, a0_addr + gks * 32);
                ldsm_x4(y0, y1, y2, y3, a1_addr + gks * 32);
                mma16816(acc[0][0][0], acc[0][0][1], acc[0][0][2], acc[0][0][3],
                         x0, x1, x2, x3, w0.x, w0.y);
                mma16816(acc[0][1][0], acc[0][1][1], acc[0][1][2], acc[0][1][3],
                         x0, x1, x2, x3, w0.z, w0.w);
                mma16816(acc[0][2][0], acc[0][2][1], acc[0][2][2], acc[0][2][3],
                         x0, x1, x2, x3, w1.x, w1.y);
                mma16816(acc[0][3][0], acc[0][3][1], acc[0][3][2], acc[0][3][3],
                         x0, x1, x2, x3, w1.z, w1.w);
                mma16816(acc[1][0][0], acc[1][0][1], acc[1][0][2], acc[1][0][3],
                         y0, y1, y2, y3, w0.x, w0.y);
                mma16816(acc[1][1][0], acc[1][1][1], acc[1][1][2], acc[1][1][3],
                         y0, y1, y2, y3, w0.z, w0.w);
                mma16816(acc[1][2][0], acc[1][2][1], acc[1][2][2], acc[1][2][3],
                         y0, y1, y2, y3, w1.x, w1.y);
                mma16816(acc[1][3][0], acc[1][3][1], acc[1][3][2], acc[1][3][3],
                         y0, y1, y2, y3, w1.z, w1.w);
            }

            __syncthreads();   // s_h consumed; F region reusable for reduction
            float* red = (float*)(smem + SM_F);   // [32 i][4 ot][32 lane]

            if (khalf == 1) {
                #pragma unroll
                for (int i = 0; i < 32; ++i)
                    red[(i * 4 + ot) * 32 + lane] = acc[i >> 4][(i >> 2) & 3][i & 3];
            }
            __syncthreads();

            if (khalf == 0) {
                const int gid = lane >> 2;
                const int tig = lane & 3;
                #pragma unroll
                for (int qt = 0; qt < 2; ++qt) {
                    const int qA = q0 + qt * 16 + gid;
                    #pragma unroll
                    for (int nt = 0; nt < 4; ++nt) {
                        const int o = o0 + nt * 8 + tig * 2;
                        const float2 bv = *(const float2*)(s_bias + o);
                        const int ib = qt * 16 + nt * 4;
                        float2 r0, r1;
                        r0.x = acc[qt][nt][0] + red[((ib + 0) * 4 + ot) * 32 + lane] + bv.x;
                        r0.y = acc[qt][nt][1] + red[((ib + 1) * 4 + ot) * 32 + lane] + bv.y;
                        r1.x = acc[qt][nt][2] + red[((ib + 2) * 4 + ot) * 32 + lane] + bv.x;
                        r1.y = acc[qt][nt][3] + red[((ib + 3) * 4 + ot) * 32 + lane] + bv.y;
                        *(float2*)(out + ((size_t)(b * N_ + qA))     * COUT + o) = r0;
                        *(float2*)(out + ((size_t)(b * N_ + qA + 8)) * COUT + o) = r1;
                    }
                }
            }
        }
        // loop-top __syncthreads() of next iteration provides cross-tile safety
    }
}

// ---------------- launch ----------------
extern "C" void kernel_launch(void* const* d_in, const int* in_sizes, int n_in,
                              void* d_out, int out_size) {
    const float* qp   = (const float*)d_in[0];
    const float* sp   = (const float*)d_in[1];
    const float* sf   = (const float*)d_in[2];
    const int*   nidx = (const int*)  d_in[3];
    const float* kp   = (const float*)d_in[4];
    const float* W    = (const float*)d_in[5];
    const float* bias = (const float*)d_in[6];
    float* out = (float*)d_out;

    static bool attr_set = false;
    if (!attr_set) {
        cudaFuncSetAttribute(kpconv_main,
                             cudaFuncAttributeMaxDynamicSharedMemorySize,
                             SMEM_TOTAL);
        attr_set = true;
    }

    convert_all<<<(CVT_TOTAL + 255) / 256, 256>>>(W, sf, sp);
    kpconv_main<<<GRID_MAIN, NTH, SMEM_TOTAL>>>(qp, nidx, kp, bias, out);
}